// round 6
// baseline (speedup 1.0000x reference)
#include <cuda_runtime.h>
#include <cuda_bf16.h>
#include <cstdint>

// ---------------------------------------------------------------------------
// AttentionGate: qp=(q@Wq+bq)*scale ; kp=k@Wk+bk ; vp=v@Wv+bv
//                out = softmax(qp @ kp^T) @ vp
// B=8, S=2048, d=512 (all dims fixed; no bounds checks needed).
// Unfused fp32 baseline: 3x proj GEMM -> batched NT GEMM -> softmax -> NN GEMM
// ---------------------------------------------------------------------------

#define BATCH 8
#define SEQ   2048
#define DIM   512
#define MTOT  (BATCH * SEQ)   // 16384

// Scratch (static __device__ globals: the sanctioned allocation-free path)
__device__ float g_qp[(size_t)MTOT * DIM];                    // 32 MB
__device__ float g_kp[(size_t)MTOT * DIM];                    // 32 MB
__device__ float g_vp[(size_t)MTOT * DIM];                    // 32 MB
__device__ float g_sc[(size_t)BATCH * SEQ * SEQ];             // 128 MB

// ---------------------------------------------------------------------------
// 128x128x8 SGEMM, 256 threads, 8x8 microtile per thread.
//   C[M,N] = (A[M,K] * op(B) + bias) * alpha      op(B) = B or B^T
//   TB=false: B is [K,N] row-major (ldb = N stride)
//   TB=true : B is [N,K] row-major (C = A * B^T)
// Grid: (N/128, M/128, batch). All dims divide exactly for our shapes.
// ---------------------------------------------------------------------------
template<bool TB, bool HAS_BIAS>
__global__ void __launch_bounds__(256)
sgemm_tile(const float* __restrict__ A, const float* __restrict__ B,
           const float* __restrict__ bias, float* __restrict__ C,
           int K, int lda, int ldb, int ldc,
           long long strideA, long long strideB, long long strideC,
           float alpha)
{
    __shared__ float smA[8][128];
    __shared__ float smB[8][128];

    const int t  = threadIdx.x;
    const long long bz = blockIdx.z;
    A += bz * strideA;
    B += bz * strideB;
    C += bz * strideC;

    const int m0 = blockIdx.y * 128;
    const int n0 = blockIdx.x * 128;

    // A-tile (and B-tile in TB mode) loader mapping: 128 rows x 8 k-cols
    const int lr = t >> 1;            // 0..127
    const int lc = (t & 1) << 2;      // 0 or 4
    // B-tile loader mapping for NN mode: 8 k-rows x 128 n-cols
    const int brow = t >> 5;          // 0..7
    const int bcol = (t & 31) << 2;   // 0..124

    const int tx = t & 15;            // col group
    const int ty = t >> 4;            // row group

    float acc[8][8];
#pragma unroll
    for (int i = 0; i < 8; i++)
#pragma unroll
        for (int j = 0; j < 8; j++) acc[i][j] = 0.f;

    const float* Aptr = A + (long long)(m0 + lr) * lda + lc;
    const float* Bptr = TB ? (B + (long long)(n0 + lr) * ldb + lc)
                           : (B + (long long)brow * ldb + n0 + bcol);

    for (int k0 = 0; k0 < K; k0 += 8) {
        float4 av = *(const float4*)(Aptr + k0);
        smA[lc + 0][lr] = av.x;
        smA[lc + 1][lr] = av.y;
        smA[lc + 2][lr] = av.z;
        smA[lc + 3][lr] = av.w;
        if (TB) {
            float4 bv = *(const float4*)(Bptr + k0);
            smB[lc + 0][lr] = bv.x;
            smB[lc + 1][lr] = bv.y;
            smB[lc + 2][lr] = bv.z;
            smB[lc + 3][lr] = bv.w;
        } else {
            float4 bv = *(const float4*)(Bptr + (long long)k0 * ldb);
            *(float4*)&smB[brow][bcol] = bv;
        }
        __syncthreads();

#pragma unroll
        for (int kk = 0; kk < 8; kk++) {
            float a[8], b[8];
            *(float4*)&a[0] = *(const float4*)&smA[kk][(ty << 2)];
            *(float4*)&a[4] = *(const float4*)&smA[kk][64 + (ty << 2)];
            *(float4*)&b[0] = *(const float4*)&smB[kk][(tx << 2)];
            *(float4*)&b[4] = *(const float4*)&smB[kk][64 + (tx << 2)];
#pragma unroll
            for (int i = 0; i < 8; i++)
#pragma unroll
                for (int j = 0; j < 8; j++)
                    acc[i][j] = fmaf(a[i], b[j], acc[i][j]);
        }
        __syncthreads();
    }

    // Epilogue: (acc + bias) * alpha, float4 stores.
#pragma unroll
    for (int i = 0; i < 8; i++) {
        const int ri = m0 + ((i < 4) ? ((ty << 2) + i) : (64 + (ty << 2) + i - 4));
        float* Crow = C + (long long)ri * ldc + n0;
#pragma unroll
        for (int half = 0; half < 2; half++) {
            const int jb = half * 4;
            const int cb = half * 64 + (tx << 2);
            float b0 = 0.f, b1 = 0.f, b2 = 0.f, b3 = 0.f;
            if (HAS_BIAS) {
                b0 = bias[n0 + cb + 0];
                b1 = bias[n0 + cb + 1];
                b2 = bias[n0 + cb + 2];
                b3 = bias[n0 + cb + 3];
            }
            float4 o;
            o.x = (acc[i][jb + 0] + b0) * alpha;
            o.y = (acc[i][jb + 1] + b1) * alpha;
            o.z = (acc[i][jb + 2] + b2) * alpha;
            o.w = (acc[i][jb + 3] + b3) * alpha;
            *(float4*)(Crow + cb) = o;
        }
    }
}

// ---------------------------------------------------------------------------
// Row softmax: one block per row of 2048 floats. 256 threads, 8 elems each.
// ---------------------------------------------------------------------------
__global__ void __launch_bounds__(256)
softmax_rows(float* __restrict__ S)
{
    float* row = S + (size_t)blockIdx.x * SEQ;
    const int t = threadIdx.x;

    float v[8];
    float m = -3.4e38f;
#pragma unroll
    for (int i = 0; i < 8; i++) {
        v[i] = row[t + i * 256];
        m = fmaxf(m, v[i]);
    }

    __shared__ float red_m[8];
    __shared__ float red_s[8];

#pragma unroll
    for (int o = 16; o; o >>= 1)
        m = fmaxf(m, __shfl_xor_sync(0xffffffffu, m, o));
    if ((t & 31) == 0) red_m[t >> 5] = m;
    __syncthreads();
    m = red_m[0];
#pragma unroll
    for (int w = 1; w < 8; w++) m = fmaxf(m, red_m[w]);

    float s = 0.f;
#pragma unroll
    for (int i = 0; i < 8; i++) {
        v[i] = __expf(v[i] - m);
        s += v[i];
    }
#pragma unroll
    for (int o = 16; o; o >>= 1)
        s += __shfl_xor_sync(0xffffffffu, s, o);
    if ((t & 31) == 0) red_s[t >> 5] = s;
    __syncthreads();
    s = 0.f;
#pragma unroll
    for (int w = 0; w < 8; w++) s += red_s[w];

    const float inv = 1.0f / s;
#pragma unroll
    for (int i = 0; i < 8; i++)
        row[t + i * 256] = v[i] * inv;
}

// ---------------------------------------------------------------------------
// Launch: q,k,v,Wq,bq,Wk,bk,Wv,bv (metadata order). Output fp32 [B,S,512].
// ---------------------------------------------------------------------------
extern "C" void kernel_launch(void* const* d_in, const int* in_sizes, int n_in,
                              void* d_out, int out_size)
{
    const float* q  = (const float*)d_in[0];
    const float* k  = (const float*)d_in[1];
    const float* v  = (const float*)d_in[2];
    const float* Wq = (const float*)d_in[3];
    const float* bq = (const float*)d_in[4];
    const float* Wk = (const float*)d_in[5];
    const float* bk = (const float*)d_in[6];
    const float* Wv = (const float*)d_in[7];
    const float* bv = (const float*)d_in[8];
    float* out = (float*)d_out;

    float *qp, *kp, *vp, *sc;
    cudaGetSymbolAddress((void**)&qp, g_qp);
    cudaGetSymbolAddress((void**)&kp, g_kp);
    cudaGetSymbolAddress((void**)&vp, g_vp);
    cudaGetSymbolAddress((void**)&sc, g_sc);

    const float scale = 0.04419417382415922f;   // 1/sqrt(512), folded into qp

    const dim3 blk(256);

    // Projections: C[16384,512] = A[16384,512] x W[512,512] + b
    sgemm_tile<false, true><<<dim3(4, 128, 1), blk>>>(
        q, Wq, bq, qp, DIM, DIM, DIM, DIM, 0, 0, 0, scale);
    sgemm_tile<false, true><<<dim3(4, 128, 1), blk>>>(
        k, Wk, bk, kp, DIM, DIM, DIM, DIM, 0, 0, 0, 1.0f);
    sgemm_tile<false, true><<<dim3(4, 128, 1), blk>>>(
        v, Wv, bv, vp, DIM, DIM, DIM, DIM, 0, 0, 0, 1.0f);

    // Scores: per batch, S[2048,2048] = qp[2048,512] x kp[2048,512]^T
    sgemm_tile<true, false><<<dim3(16, 16, BATCH), blk>>>(
        qp, kp, nullptr, sc, DIM, DIM, DIM, SEQ,
        (long long)SEQ * DIM, (long long)SEQ * DIM, (long long)SEQ * SEQ, 1.0f);

    // Softmax over keys
    softmax_rows<<<BATCH * SEQ, blk>>>(sc);

    // Output: per batch, O[2048,512] = P[2048,2048] x vp[2048,512]
    sgemm_tile<false, false><<<dim3(4, 16, BATCH), blk>>>(
        sc, vp, nullptr, out, SEQ, SEQ, DIM, DIM,
        (long long)SEQ * SEQ, (long long)SEQ * DIM, (long long)SEQ * DIM, 1.0f);
}

// round 10
// speedup vs baseline: 2.7146x; 2.7146x over previous
#include <cuda_runtime.h>
#include <cuda_bf16.h>
#include <cstdint>

// ===========================================================================
// AttentionGate via mma.sync bf16 split-precision (bf16x3) GEMMs.
// (tcgen05 is unavailable: harness PTX targets sm_103, not sm_103a.)
//   x = hi + lo (bf16 each);  x*y ~= hi*hi + hi*lo + lo*hi  (fp32 accum)
// Pipeline:
//   split(q,k,v) ; transpose+split(Wq,Wk,Wv)
//   qp = (q Wq + bq)*scale   [split-bf16 out]
//   kp =  k Wk + bk          [split-bf16 out]
//   vpT = Wv^T v^T + bv      [split-bf16 out, (d, tokens) layout]
//   S  = qp kp^T             [fp32]
//   P  = softmax(S)          [split-bf16 out]
//   O  = P vp                [fp32 -> d_out]
// ===========================================================================

#define BATCH 8
#define SEQ   2048
#define DIM   512
#define MTOT  (BATCH * SEQ)          // 16384
#define NTOK  ((size_t)MTOT * DIM)   // 8388608

// ---------------- scratch (__device__ globals; allocation-free) -----------
__device__ __nv_bfloat16 g_qh[NTOK],  g_ql[NTOK];
__device__ __nv_bfloat16 g_kh[NTOK],  g_kl[NTOK];
__device__ __nv_bfloat16 g_vh[NTOK],  g_vl[NTOK];
__device__ __nv_bfloat16 g_wqh[DIM*DIM], g_wql[DIM*DIM];
__device__ __nv_bfloat16 g_wkh[DIM*DIM], g_wkl[DIM*DIM];
__device__ __nv_bfloat16 g_wvh[DIM*DIM], g_wvl[DIM*DIM];
__device__ __nv_bfloat16 g_qph[NTOK], g_qpl[NTOK];
__device__ __nv_bfloat16 g_kph[NTOK], g_kpl[NTOK];
__device__ __nv_bfloat16 g_vth[NTOK], g_vtl[NTOK];
__device__ float         g_sc[(size_t)BATCH * SEQ * SEQ];     // 128 MB
__device__ __nv_bfloat16 g_ph[(size_t)BATCH * SEQ * SEQ];
__device__ __nv_bfloat16 g_pl[(size_t)BATCH * SEQ * SEQ];

// ---------------- PTX helpers (sm_80-era: legal on plain sm_103) ----------
__device__ __forceinline__ uint32_t s2u(const void* p) {
    uint32_t a;
    asm("{ .reg .u64 t; cvta.to.shared.u64 t, %1; cvt.u32.u64 %0, t; }"
        : "=r"(a) : "l"(p));
    return a;
}
__device__ __forceinline__ void cpa16(uint32_t s, const void* g) {
    asm volatile("cp.async.cg.shared.global [%0], [%1], 16;" :: "r"(s), "l"(g));
}
__device__ __forceinline__ void cpa_commit() {
    asm volatile("cp.async.commit_group;" ::: "memory");
}
template <int N>
__device__ __forceinline__ void cpa_wait() {
    asm volatile("cp.async.wait_group %0;" :: "n"(N) : "memory");
}
__device__ __forceinline__ void ldsm4(uint32_t* r, uint32_t a) {
    asm volatile("ldmatrix.sync.aligned.m8n8.x4.shared.b16 {%0,%1,%2,%3}, [%4];"
        : "=r"(r[0]), "=r"(r[1]), "=r"(r[2]), "=r"(r[3]) : "r"(a));
}
__device__ __forceinline__ void mma_bf16(float* d, const uint32_t* a, const uint32_t* b) {
    asm volatile(
        "mma.sync.aligned.m16n8k16.row.col.f32.bf16.bf16.f32 "
        "{%0,%1,%2,%3},{%4,%5,%6,%7},{%8,%9},{%0,%1,%2,%3};"
        : "+f"(d[0]), "+f"(d[1]), "+f"(d[2]), "+f"(d[3])
        : "r"(a[0]), "r"(a[1]), "r"(a[2]), "r"(a[3]), "r"(b[0]), "r"(b[1]));
}
__device__ __forceinline__ void split2(float x, __nv_bfloat16& h, __nv_bfloat16& l) {
    h = __float2bfloat16(x);
    l = __float2bfloat16(x - __bfloat162float(h));
}

// ===========================================================================
// mma.sync bf16x3 GEMM:  C[M,N] = (A * B^T + bias) * scale  (per grid.z batch)
//   A: [M,K] K-major hi/lo bf16,  B: [N,K] K-major hi/lo bf16
//   CTA tile 128x128, KC=64, 2-stage cp.async, 8 warps (2m x 4n), 64x32/warp.
//   BIAS_MODE: 0 none, 1 per-col bias[n], 2 per-row bias[m]
//   SPLIT_OUT: false -> fp32 C ; true -> hi/lo bf16 pair
// ===========================================================================
#define BM 128
#define BN 128
#define KC 64
#define STAGE_BYTES 65536            // Ah 16K | Al 16K | Bh 16K | Bl 16K
#define GEMM_SMEM   (2 * STAGE_BYTES)

template <int BIAS_MODE, bool SPLIT_OUT>
__global__ void __launch_bounds__(256, 1)
gemm3(const __nv_bfloat16* __restrict__ Ah, const __nv_bfloat16* __restrict__ Al,
      const __nv_bfloat16* __restrict__ Bh, const __nv_bfloat16* __restrict__ Bl,
      const float* __restrict__ bias,
      float* __restrict__ Cf, __nv_bfloat16* __restrict__ Ch, __nv_bfloat16* __restrict__ Cl,
      int K, int lda, int ldb, int ldc,
      long long sA, long long sB, long long sC, float scale)
{
    extern __shared__ __align__(1024) char smem[];
    const uint32_t sb = s2u(smem);

    const int tid = threadIdx.x, wid = tid >> 5, lane = tid & 31;
    const long long z = blockIdx.z;
    const int m0 = blockIdx.y * BM, n0 = blockIdx.x * BN;

    const __nv_bfloat16* pAh = Ah + z * sA + (long long)m0 * lda;
    const __nv_bfloat16* pAl = Al + z * sA + (long long)m0 * lda;
    const __nv_bfloat16* pBh = Bh + z * sB + (long long)n0 * ldb;
    const __nv_bfloat16* pBl = Bl + z * sB + (long long)n0 * ldb;

    // ---- stage loader: 128 rows x 8 x 16B chunks per matrix, XOR swizzle
    auto load_stage = [&](int s, int k0) {
        const uint32_t st = sb + (uint32_t)s * STAGE_BYTES;
#pragma unroll
        for (int j = 0; j < 4; j++) {
            const int i = tid + 256 * j;
            const int r = i >> 3, ch = i & 7;
            const uint32_t o = (uint32_t)r * 128 + (uint32_t)((ch ^ (r & 7)) << 4);
            const long long ga = (long long)r * lda + k0 + ch * 8;
            const long long gb = (long long)r * ldb + k0 + ch * 8;
            cpa16(st + o,          pAh + ga);
            cpa16(st + 16384 + o,  pAl + ga);
            cpa16(st + 32768 + o,  pBh + gb);
            cpa16(st + 49152 + o,  pBl + gb);
        }
    };

    // ---- warp/thread tiling
    const int warp_m = (wid & 1) * 64;       // 2 warps over M
    const int warp_n = (wid >> 1) * 32;      // 4 warps over N

    // ldmatrix lane address components (A: m16k16 x4 ; B: n16k16 x4)
    const int a_row = lane & 15;
    const int a_k   = lane >> 4;                       // 0/1 -> +k8
    const int b_row = (lane & 7) | ((lane & 16) >> 1);
    const int b_k   = (lane >> 3) & 1;
    const int swzA  = a_row & 7, swzB = b_row & 7;

    uint32_t rbA[4], rbB[2];
#pragma unroll
    for (int mt = 0; mt < 4; mt++) rbA[mt] = (uint32_t)(warp_m + mt * 16 + a_row) * 128;
#pragma unroll
    for (int p = 0; p < 2; p++)    rbB[p]  = (uint32_t)(warp_n + p * 16 + b_row) * 128;

    float acc[4][4][4];
#pragma unroll
    for (int mt = 0; mt < 4; mt++)
#pragma unroll
        for (int nt = 0; nt < 4; nt++)
#pragma unroll
            for (int e = 0; e < 4; e++) acc[mt][nt][e] = 0.f;

    const int NC = K / KC;
    load_stage(0, 0);  cpa_commit();
    load_stage(1, KC); cpa_commit();

    for (int c = 0; c < NC; c++) {
        const int s = c & 1;
        if (c < NC - 1) cpa_wait<1>(); else cpa_wait<0>();
        __syncthreads();

        const uint32_t st = sb + (uint32_t)s * STAGE_BYTES;
#pragma unroll
        for (int ks = 0; ks < 4; ks++) {
            const uint32_t chA = (uint32_t)(((2 * ks + a_k) ^ swzA) << 4);
            const uint32_t chB = (uint32_t)(((2 * ks + b_k) ^ swzB) << 4);

            uint32_t ah[4][4], al[4][4];
#pragma unroll
            for (int mt = 0; mt < 4; mt++) {
                ldsm4(ah[mt], st +         rbA[mt] + chA);
                ldsm4(al[mt], st + 16384 + rbA[mt] + chA);
            }
            uint32_t bh[2][4], bl[2][4];
#pragma unroll
            for (int p = 0; p < 2; p++) {
                ldsm4(bh[p], st + 32768 + rbB[p] + chB);
                ldsm4(bl[p], st + 49152 + rbB[p] + chB);
            }
#pragma unroll
            for (int mt = 0; mt < 4; mt++)
#pragma unroll
                for (int nt = 0; nt < 4; nt++) {
                    const uint32_t* bhp = &bh[nt >> 1][(nt & 1) * 2];
                    const uint32_t* blp = &bl[nt >> 1][(nt & 1) * 2];
                    mma_bf16(acc[mt][nt], ah[mt], bhp);   // hi*hi
                    mma_bf16(acc[mt][nt], ah[mt], blp);   // hi*lo
                    mma_bf16(acc[mt][nt], al[mt], bhp);   // lo*hi
                }
        }
        __syncthreads();                                  // stage s fully read
        if (c + 2 < NC) { load_stage(s, (c + 2) * KC); cpa_commit(); }
    }

    // ---- epilogue straight from registers
    const int r0 = m0 + warp_m + (lane >> 2);
    const int c0 = n0 + warp_n + (lane & 3) * 2;
#pragma unroll
    for (int nt = 0; nt < 4; nt++) {
        const int col = c0 + nt * 8;
        float bc0 = 0.f, bc1 = 0.f;
        if (BIAS_MODE == 1) { bc0 = bias[col]; bc1 = bias[col + 1]; }
#pragma unroll
        for (int mt = 0; mt < 4; mt++) {
#pragma unroll
            for (int half = 0; half < 2; half++) {
                const int row = r0 + mt * 16 + half * 8;
                float br = 0.f;
                if (BIAS_MODE == 2) br = bias[row];
                float x0 = acc[mt][nt][2 * half + 0];
                float x1 = acc[mt][nt][2 * half + 1];
                if (BIAS_MODE == 1) { x0 += bc0; x1 += bc1; }
                if (BIAS_MODE == 2) { x0 += br;  x1 += br;  }
                x0 *= scale; x1 *= scale;

                const long long base = z * sC + (long long)row * ldc + col;
                if (!SPLIT_OUT) {
                    *(float2*)(Cf + base) = make_float2(x0, x1);
                } else {
                    __nv_bfloat16 h0, l0, h1, l1;
                    split2(x0, h0, l0); split2(x1, h1, l1);
                    __nv_bfloat162 hh; hh.x = h0; hh.y = h1;
                    __nv_bfloat162 ll; ll.x = l0; ll.y = l1;
                    *(__nv_bfloat162*)(Ch + base) = hh;
                    *(__nv_bfloat162*)(Cl + base) = ll;
                }
            }
        }
    }
}

// ---------------- fp32 -> hi/lo bf16 elementwise split --------------------
__global__ void __launch_bounds__(256)
split_kernel(const float* __restrict__ x, __nv_bfloat16* __restrict__ h,
             __nv_bfloat16* __restrict__ l, int n4)
{
    int i = blockIdx.x * 256 + threadIdx.x;
    if (i >= n4) return;
    float4 a = ((const float4*)x)[i];
    __nv_bfloat16 h0,l0,h1,l1,h2,l2,h3,l3;
    split2(a.x, h0, l0); split2(a.y, h1, l1);
    split2(a.z, h2, l2); split2(a.w, h3, l3);
    __nv_bfloat162 p0; p0.x=h0; p0.y=h1;  __nv_bfloat162 p1; p1.x=h2; p1.y=h3;
    __nv_bfloat162 q0; q0.x=l0; q0.y=l1;  __nv_bfloat162 q1; q1.x=l2; q1.y=l3;
    ((__nv_bfloat162*)h)[2*i] = p0; ((__nv_bfloat162*)h)[2*i+1] = p1;
    ((__nv_bfloat162*)l)[2*i] = q0; ((__nv_bfloat162*)l)[2*i+1] = q1;
}

// ---------------- W [K,N] -> W^T [N,K] hi/lo bf16 --------------------------
__global__ void __launch_bounds__(256)
tsplitW(const float* __restrict__ W, __nv_bfloat16* __restrict__ Th,
        __nv_bfloat16* __restrict__ Tl)
{
    __shared__ float t[32][33];
    const int bx = blockIdx.x * 32;   // n
    const int by = blockIdx.y * 32;   // k
    const int x = threadIdx.x & 31, y = threadIdx.x >> 5;   // 32 x 8
#pragma unroll
    for (int j = 0; j < 32; j += 8)
        t[y + j][x] = W[(long long)(by + y + j) * DIM + bx + x];
    __syncthreads();
#pragma unroll
    for (int j = 0; j < 32; j += 8) {
        float v = t[x][y + j];
        __nv_bfloat16 h, l; split2(v, h, l);
        long long o = (long long)(bx + y + j) * DIM + by + x;
        Th[o] = h; Tl[o] = l;
    }
}

// ---------------- softmax rows (fp32 in) -> hi/lo bf16 P -------------------
__global__ void __launch_bounds__(256)
softmax_split(const float* __restrict__ S, __nv_bfloat16* __restrict__ Ph,
              __nv_bfloat16* __restrict__ Pl)
{
    const float* row = S + (size_t)blockIdx.x * SEQ;
    const int t = threadIdx.x;

    float v[8];
    float m = -3.4e38f;
#pragma unroll
    for (int i = 0; i < 8; i++) { v[i] = row[t + i * 256]; m = fmaxf(m, v[i]); }

    __shared__ float red[8];
#pragma unroll
    for (int o = 16; o; o >>= 1) m = fmaxf(m, __shfl_xor_sync(0xffffffffu, m, o));
    if ((t & 31) == 0) red[t >> 5] = m;
    __syncthreads();
    m = red[0];
#pragma unroll
    for (int w = 1; w < 8; w++) m = fmaxf(m, red[w]);
    __syncthreads();

    float s = 0.f;
#pragma unroll
    for (int i = 0; i < 8; i++) { v[i] = __expf(v[i] - m); s += v[i]; }
#pragma unroll
    for (int o = 16; o; o >>= 1) s += __shfl_xor_sync(0xffffffffu, s, o);
    if ((t & 31) == 0) red[t >> 5] = s;
    __syncthreads();
    s = 0.f;
#pragma unroll
    for (int w = 0; w < 8; w++) s += red[w];

    const float inv = 1.0f / s;
    const size_t rb = (size_t)blockIdx.x * SEQ;
#pragma unroll
    for (int i = 0; i < 8; i++) {
        float p = v[i] * inv;
        __nv_bfloat16 h, l; split2(p, h, l);
        Ph[rb + t + i * 256] = h;
        Pl[rb + t + i * 256] = l;
    }
}

// ===========================================================================
extern "C" void kernel_launch(void* const* d_in, const int* in_sizes, int n_in,
                              void* d_out, int out_size)
{
    const float* q  = (const float*)d_in[0];
    const float* k  = (const float*)d_in[1];
    const float* v  = (const float*)d_in[2];
    const float* Wq = (const float*)d_in[3];
    const float* bq = (const float*)d_in[4];
    const float* Wk = (const float*)d_in[5];
    const float* bk = (const float*)d_in[6];
    const float* Wv = (const float*)d_in[7];
    const float* bv = (const float*)d_in[8];
    float* out = (float*)d_out;

    __nv_bfloat16 *qh,*ql,*kh,*kl,*vh,*vl, *wqh,*wql,*wkh,*wkl,*wvh,*wvl;
    __nv_bfloat16 *qph,*qpl,*kph,*kpl,*vth,*vtl, *ph,*pl;
    float* sc;
    cudaGetSymbolAddress((void**)&qh,  g_qh);  cudaGetSymbolAddress((void**)&ql,  g_ql);
    cudaGetSymbolAddress((void**)&kh,  g_kh);  cudaGetSymbolAddress((void**)&kl,  g_kl);
    cudaGetSymbolAddress((void**)&vh,  g_vh);  cudaGetSymbolAddress((void**)&vl,  g_vl);
    cudaGetSymbolAddress((void**)&wqh, g_wqh); cudaGetSymbolAddress((void**)&wql, g_wql);
    cudaGetSymbolAddress((void**)&wkh, g_wkh); cudaGetSymbolAddress((void**)&wkl, g_wkl);
    cudaGetSymbolAddress((void**)&wvh, g_wvh); cudaGetSymbolAddress((void**)&wvl, g_wvl);
    cudaGetSymbolAddress((void**)&qph, g_qph); cudaGetSymbolAddress((void**)&qpl, g_qpl);
    cudaGetSymbolAddress((void**)&kph, g_kph); cudaGetSymbolAddress((void**)&kpl, g_kpl);
    cudaGetSymbolAddress((void**)&vth, g_vth); cudaGetSymbolAddress((void**)&vtl, g_vtl);
    cudaGetSymbolAddress((void**)&ph,  g_ph);  cudaGetSymbolAddress((void**)&pl,  g_pl);
    cudaGetSymbolAddress((void**)&sc,  g_sc);

    cudaFuncSetAttribute(gemm3<1, true>,  cudaFuncAttributeMaxDynamicSharedMemorySize, GEMM_SMEM);
    cudaFuncSetAttribute(gemm3<2, true>,  cudaFuncAttributeMaxDynamicSharedMemorySize, GEMM_SMEM);
    cudaFuncSetAttribute(gemm3<0, false>, cudaFuncAttributeMaxDynamicSharedMemorySize, GEMM_SMEM);

    const float qscale = 0.04419417382415922f;   // 1/sqrt(512)
    const int n4 = (int)(NTOK / 4);

    // 1) split inputs to hi/lo bf16
    split_kernel<<<(n4 + 255) / 256, 256>>>(q, qh, ql, n4);
    split_kernel<<<(n4 + 255) / 256, 256>>>(k, kh, kl, n4);
    split_kernel<<<(n4 + 255) / 256, 256>>>(v, vh, vl, n4);

    // 2) transpose + split weights (W[k,n] -> WT[n,k])
    tsplitW<<<dim3(16, 16), 256>>>(Wq, wqh, wql);
    tsplitW<<<dim3(16, 16), 256>>>(Wk, wkh, wkl);
    tsplitW<<<dim3(16, 16), 256>>>(Wv, wvh, wvl);

    // 3) projections
    // qp[t,d] = (sum_h q[t,h] WqT[d,h] + bq[d]) * qscale  -> split bf16
    gemm3<1, true><<<dim3(4, 128, 1), 256, GEMM_SMEM>>>(
        qh, ql, wqh, wql, bq, nullptr, qph, qpl,
        DIM, DIM, DIM, DIM, 0, 0, 0, qscale);
    gemm3<1, true><<<dim3(4, 128, 1), 256, GEMM_SMEM>>>(
        kh, kl, wkh, wkl, bk, nullptr, kph, kpl,
        DIM, DIM, DIM, DIM, 0, 0, 0, 1.0f);
    // vpT[d,t] = sum_e WvT[d,e] v[t,e] + bv[d]  -> split bf16, ldc = 16384
    gemm3<2, true><<<dim3(128, 4, 1), 256, GEMM_SMEM>>>(
        wvh, wvl, vh, vl, bv, nullptr, vth, vtl,
        DIM, DIM, DIM, MTOT, 0, 0, 0, 1.0f);

    // 4) scores: per batch S[sq,sk] = qp . kp  (fp32)
    gemm3<0, false><<<dim3(16, 16, BATCH), 256, GEMM_SMEM>>>(
        qph, qpl, kph, kpl, nullptr, sc, nullptr, nullptr,
        DIM, DIM, DIM, SEQ,
        (long long)SEQ * DIM, (long long)SEQ * DIM, (long long)SEQ * SEQ, 1.0f);

    // 5) softmax -> split bf16 P
    softmax_split<<<BATCH * SEQ, 256>>>(sc, ph, pl);

    // 6) O = P vp : B[n=d, k=s] = vpT[d, z*2048 + s]  (ldb=16384, batch stride 2048)
    gemm3<0, false><<<dim3(4, 16, BATCH), 256, GEMM_SMEM>>>(
        ph, pl, vth, vtl, nullptr, out, nullptr, nullptr,
        SEQ, SEQ, MTOT, DIM,
        (long long)SEQ * SEQ, (long long)SEQ, (long long)SEQ * DIM, 1.0f);
}